// round 14
// baseline (speedup 1.0000x reference)
#include <cuda_runtime.h>
#include <cuda_bf16.h>
#include <cstdint>

// MHA layer: B=4, S=2048, HID=512, H=8, HD=64.
// Projections: bf16 mma.sync (m16n8k16, HMMA path — non-arch-'a', works on
// compute_103 virtual arch) with hi/lo split 3-term compensation.
// Attention: packed-f32x2 flash attention (R8 passing version, unchanged).

#define BB   4
#define SS   2048
#define HIDD 512
#define NH   8
#define HDD  64

// ---------------- scratch (__device__ globals; no allocation allowed) -------
__device__ float g_Q[BB * NH * SS * HDD];
__device__ float g_K[BB * NH * SS * HDD];
__device__ float g_V[BB * NH * SS * HDD];
__device__ float g_C[BB * SS * HIDD];

// bf16 hi/lo split buffers (activation buffer reused sequentially for q,k,v,C)
__device__ __nv_bfloat16 g_Ahi[BB * SS * HIDD];
__device__ __nv_bfloat16 g_Alo[BB * SS * HIDD];
__device__ __nv_bfloat16 g_Whi[4][HIDD * HIDD];
__device__ __nv_bfloat16 g_Wlo[4][HIDD * HIDD];

typedef unsigned long long u64;
typedef unsigned int u32;

__device__ __forceinline__ u64 pk2(float x, float y) {
    u64 r; asm("mov.b64 %0, {%1, %2};" : "=l"(r) : "f"(x), "f"(y)); return r;
}
__device__ __forceinline__ u64 ffma2(u64 a, u64 b, u64 c) {
    u64 d; asm("fma.rn.f32x2 %0, %1, %2, %3;" : "=l"(d) : "l"(a), "l"(b), "l"(c)); return d;
}
__device__ __forceinline__ u64 fmul2(u64 a, u64 b) {
    u64 d; asm("mul.rn.f32x2 %0, %1, %2;" : "=l"(d) : "l"(a), "l"(b)); return d;
}
__device__ __forceinline__ float2 up2(u64 v) {
    float2 f; asm("mov.b64 {%0, %1}, %2;" : "=f"(f.x), "=f"(f.y) : "l"(v)); return f;
}
__device__ __forceinline__ u32 smem_u32(const void* p) {
    u32 a;
    asm("{ .reg .u64 t; cvta.to.shared.u64 t, %1; cvt.u32.u64 %0, t; }" : "=r"(a) : "l"(p));
    return a;
}

// ---------------- mma.sync helpers (sm_80+ features only) -------------------
__device__ __forceinline__ void ldmx4(u32* r, u32 addr) {
    asm volatile("ldmatrix.sync.aligned.m8n8.x4.shared.b16 {%0,%1,%2,%3}, [%4];"
        : "=r"(r[0]), "=r"(r[1]), "=r"(r[2]), "=r"(r[3]) : "r"(addr));
}
__device__ __forceinline__ void ldmx2(u32* r, u32 addr) {
    asm volatile("ldmatrix.sync.aligned.m8n8.x2.shared.b16 {%0,%1}, [%2];"
        : "=r"(r[0]), "=r"(r[1]) : "r"(addr));
}
__device__ __forceinline__ void mma16816(float* c, const u32* a, const u32* b) {
    asm volatile("mma.sync.aligned.m16n8k16.row.col.f32.bf16.bf16.f32 "
        "{%0,%1,%2,%3}, {%4,%5,%6,%7}, {%8,%9}, {%0,%1,%2,%3};"
        : "+f"(c[0]), "+f"(c[1]), "+f"(c[2]), "+f"(c[3])
        : "r"(a[0]), "r"(a[1]), "r"(a[2]), "r"(a[3]), "r"(b[0]), "r"(b[1]));
}

// ---------------------------------------------------------------------------
// fp32 -> (bf16 hi, bf16 lo) split, vectorized x4
// ---------------------------------------------------------------------------
__global__ void __launch_bounds__(256) conv_split_kernel(
    const float* __restrict__ X, __nv_bfloat16* __restrict__ hi,
    __nv_bfloat16* __restrict__ lo, int n4)
{
    int i = blockIdx.x * blockDim.x + threadIdx.x;
    if (i >= n4) return;
    float4 v = ((const float4*)X)[i];
    __nv_bfloat16 h0 = __float2bfloat16(v.x), h1 = __float2bfloat16(v.y);
    __nv_bfloat16 h2 = __float2bfloat16(v.z), h3 = __float2bfloat16(v.w);
    __nv_bfloat16 l0 = __float2bfloat16(v.x - __bfloat162float(h0));
    __nv_bfloat16 l1 = __float2bfloat16(v.y - __bfloat162float(h1));
    __nv_bfloat16 l2 = __float2bfloat16(v.z - __bfloat162float(h2));
    __nv_bfloat16 l3 = __float2bfloat16(v.w - __bfloat162float(h3));
    ((__nv_bfloat162*)hi)[2 * i + 0] = __nv_bfloat162(h0, h1);
    ((__nv_bfloat162*)hi)[2 * i + 1] = __nv_bfloat162(h2, h3);
    ((__nv_bfloat162*)lo)[2 * i + 0] = __nv_bfloat162(l0, l1);
    ((__nv_bfloat162*)lo)[2 * i + 1] = __nv_bfloat162(l2, l3);
}

// ---------------------------------------------------------------------------
// Tensor-core GEMM: Y[M][512] = A @ W^T + bias, A/W as bf16 hi/lo (K-major).
// D = Ahi*Whi + Ahi*Wlo + Alo*Whi, fp32 accumulators.
// CTA tile 128x128, 8 warps (2 m x 4 n), warp tile 64x32, K-chunk 32.
// Smem padded to stride 40 bf16 (80 B) -> conflict-free ldmatrix.
// split=1 scatters rows into [B,H,S,HD]; split=0 writes [M,512].
// ---------------------------------------------------------------------------
#define PADK 40

__global__ void __launch_bounds__(256) gemm_mma_kernel(
    const __nv_bfloat16* __restrict__ Ahi, const __nv_bfloat16* __restrict__ Alo,
    const __nv_bfloat16* __restrict__ Bhi, const __nv_bfloat16* __restrict__ Blo,
    const float* __restrict__ bias, float* __restrict__ Y, int split)
{
    __shared__ __nv_bfloat16 sAh[128 * PADK];
    __shared__ __nv_bfloat16 sAl[128 * PADK];
    __shared__ __nv_bfloat16 sBh[128 * PADK];
    __shared__ __nv_bfloat16 sBl[128 * PADK];

    const int t = threadIdx.x;
    const int lane = t & 31, wid = t >> 5;
    const int wm = wid >> 2, wn = wid & 3;     // 2 x 4 warp grid
    const int m0 = blockIdx.y * 128, n0 = blockIdx.x * 128;

    float acc[4][4][4];
#pragma unroll
    for (int i = 0; i < 4; i++)
#pragma unroll
        for (int j = 0; j < 4; j++)
#pragma unroll
            for (int q = 0; q < 4; q++) acc[i][j][q] = 0.0f;

    // ldmatrix lane addressing (element offsets)
    const int arow = lane & 15;            // A: rows 0..15 of the 16-row tile
    const int acol = (lane >> 4) * 8;      // A: k-half 0 / 8
    const int brow = lane & 7;             // B: n rows 0..7
    const int bcol = ((lane >> 3) & 1) * 8; // B: k-half for lanes 0-15

    const u32 sAh_b = smem_u32(sAh), sAl_b = smem_u32(sAl);
    const u32 sBh_b = smem_u32(sBh), sBl_b = smem_u32(sBl);

    for (int kt = 0; kt < 16; kt++) {
        const int k0 = kt * 32;
        const __nv_bfloat16* aH = Ahi + (size_t)m0 * HIDD + k0;
        const __nv_bfloat16* aL = Alo + (size_t)m0 * HIDD + k0;
        const __nv_bfloat16* bH = Bhi + (size_t)n0 * HIDD + k0;
        const __nv_bfloat16* bL = Blo + (size_t)n0 * HIDD + k0;

        __syncthreads();
        // 512 uint4 (8 bf16) per 128x32 tile; 2 per thread per tile
#pragma unroll
        for (int u = 0; u < 2; u++) {
            int e = t + u * 256;
            int row = e >> 2, c8 = (e & 3) << 3;
            int dst = row * PADK + c8;
            size_t g = (size_t)row * HIDD + c8;
            *(uint4*)&sAh[dst] = *(const uint4*)(aH + g);
            *(uint4*)&sAl[dst] = *(const uint4*)(aL + g);
            *(uint4*)&sBh[dst] = *(const uint4*)(bH + g);
            *(uint4*)&sBl[dst] = *(const uint4*)(bL + g);
        }
        __syncthreads();

#pragma unroll
        for (int k16 = 0; k16 < 32; k16 += 16) {
            // B fragments (hi + lo), 4 n-tiles of 8
            u32 bh[4][2], bl[4][2];
#pragma unroll
            for (int nt = 0; nt < 4; nt++) {
                u32 off = (u32)(((wn * 32 + nt * 8 + brow) * PADK + k16 + bcol) * 2);
                ldmx2(bh[nt], sBh_b + off);
                ldmx2(bl[nt], sBl_b + off);
            }
            // A hi fragments, 4 m-tiles of 16
            u32 ah[4][4];
#pragma unroll
            for (int mt = 0; mt < 4; mt++) {
                u32 off = (u32)(((wm * 64 + mt * 16 + arow) * PADK + k16 + acol) * 2);
                ldmx4(ah[mt], sAh_b + off);
            }
#pragma unroll
            for (int mt = 0; mt < 4; mt++)
#pragma unroll
                for (int nt = 0; nt < 4; nt++) {
                    mma16816(acc[mt][nt], ah[mt], bh[nt]);   // hi*hi
                    mma16816(acc[mt][nt], ah[mt], bl[nt]);   // hi*lo
                }
            // A lo fragments (reuse ah registers)
#pragma unroll
            for (int mt = 0; mt < 4; mt++) {
                u32 off = (u32)(((wm * 64 + mt * 16 + arow) * PADK + k16 + acol) * 2);
                ldmx4(ah[mt], sAl_b + off);
            }
#pragma unroll
            for (int mt = 0; mt < 4; mt++)
#pragma unroll
                for (int nt = 0; nt < 4; nt++)
                    mma16816(acc[mt][nt], ah[mt], bh[nt]);   // lo*hi
        }
    }

    // Epilogue: c0,c1 -> (row = m+lane/4, n = 2*(lane%4)); c2,c3 -> row+8
    const int erow = lane >> 2, ecol = (lane & 3) * 2;
#pragma unroll
    for (int mt = 0; mt < 4; mt++) {
#pragma unroll
        for (int nt = 0; nt < 4; nt++) {
            int mb = m0 + wm * 64 + mt * 16 + erow;
            int n  = n0 + wn * 32 + nt * 8 + ecol;
            float2 bb = *(const float2*)(bias + n);
            float2 o0 = make_float2(acc[mt][nt][0] + bb.x, acc[mt][nt][1] + bb.y);
            float2 o1 = make_float2(acc[mt][nt][2] + bb.x, acc[mt][nt][3] + bb.y);
            if (split) {
                int h = n >> 6, d = n & 63;
                int bi0 = mb >> 11, s0 = mb & (SS - 1);
                int m1 = mb + 8, bi1 = m1 >> 11, s1 = m1 & (SS - 1);
                *(float2*)(Y + ((((size_t)bi0 * NH + h) * SS + s0) * HDD + d)) = o0;
                *(float2*)(Y + ((((size_t)bi1 * NH + h) * SS + s1) * HDD + d)) = o1;
            } else {
                *(float2*)(Y + (size_t)mb * HIDD + n) = o0;
                *(float2*)(Y + (size_t)(mb + 8) * HIDD + n) = o1;
            }
        }
    }
}

// ---------------------------------------------------------------------------
// Flash attention (unchanged from R8 passing kernel)
// ---------------------------------------------------------------------------
__global__ void __launch_bounds__(256) attn_kernel(const int* __restrict__ mask)
{
    __shared__ float Qs[64 * 64];
    __shared__ float KPs[64 * 64];
    __shared__ float Vs[64 * 64];

    const int t  = threadIdx.x;
    const int tx = t & 15, ty = t >> 4;
    const int qt = blockIdx.x, h = blockIdx.y, b = blockIdx.z;
    const int lr = t & 63;
    const int lq = t >> 6;

    const float* Qb = g_Q + ((size_t)(b * NH + h) * SS) * HDD;
    const float* Kb = g_K + ((size_t)(b * NH + h) * SS) * HDD;
    const float* Vb = g_V + ((size_t)(b * NH + h) * SS) * HDD;
    const int*   mb = mask + b * SS;

#pragma unroll
    for (int u = 0; u < 4; u++) {
        int d4 = lq * 16 + u * 4;
        float4 v = *(const float4*)(Qb + (size_t)(qt * 64 + lr) * HDD + d4);
        Qs[(d4 + 0) * 64 + lr] = v.x; Qs[(d4 + 1) * 64 + lr] = v.y;
        Qs[(d4 + 2) * 64 + lr] = v.z; Qs[(d4 + 3) * 64 + lr] = v.w;
    }

    u64 o2[4][2];
    float rm[4], rl[4];
#pragma unroll
    for (int i = 0; i < 4; i++) {
        o2[i][0] = 0ULL; o2[i][1] = 0ULL;
        rm[i] = -1e30f; rl[i] = 0.0f;
    }

    for (int kt = 0; kt < SS / 64; kt++) {
        __syncthreads();
#pragma unroll
        for (int u = 0; u < 4; u++) {
            int d4 = lq * 16 + u * 4;
            float4 v = *(const float4*)(Kb + (size_t)(kt * 64 + lr) * HDD + d4);
            KPs[(d4 + 0) * 64 + lr] = v.x; KPs[(d4 + 1) * 64 + lr] = v.y;
            KPs[(d4 + 2) * 64 + lr] = v.z; KPs[(d4 + 3) * 64 + lr] = v.w;
        }
#pragma unroll
        for (int u = 0; u < 4; u++) {
            int f = t + u * 256;
            *(float4*)&Vs[f * 4] = *(const float4*)(Vb + (size_t)kt * 64 * HDD + f * 4);
        }
        __syncthreads();

        u64 s2[4][2];
#pragma unroll
        for (int i = 0; i < 4; i++) { s2[i][0] = 0ULL; s2[i][1] = 0ULL; }
#pragma unroll 16
        for (int d = 0; d < 64; d++) {
            float4 a4     = *(const float4*)&Qs[d * 64 + ty * 4];
            ulonglong2 b2 = *(const ulonglong2*)&KPs[d * 64 + tx * 4];
            u64 ap;
            ap = pk2(a4.x, a4.x); s2[0][0] = ffma2(ap, b2.x, s2[0][0]); s2[0][1] = ffma2(ap, b2.y, s2[0][1]);
            ap = pk2(a4.y, a4.y); s2[1][0] = ffma2(ap, b2.x, s2[1][0]); s2[1][1] = ffma2(ap, b2.y, s2[1][1]);
            ap = pk2(a4.z, a4.z); s2[2][0] = ffma2(ap, b2.x, s2[2][0]); s2[2][1] = ffma2(ap, b2.y, s2[2][1]);
            ap = pk2(a4.w, a4.w); s2[3][0] = ffma2(ap, b2.x, s2[3][0]); s2[3][1] = ffma2(ap, b2.y, s2[3][1]);
        }

        float sv[4][4];
        int4 mk = *(const int4*)(mb + kt * 64 + tx * 4);
#pragma unroll
        for (int i = 0; i < 4; i++) {
            float2 u0 = up2(s2[i][0]), u1 = up2(s2[i][1]);
            sv[i][0] = u0.x * 0.125f; sv[i][1] = u0.y * 0.125f;
            sv[i][2] = u1.x * 0.125f; sv[i][3] = u1.y * 0.125f;
        }
        if (mk.x == 0) { sv[0][0] = sv[1][0] = sv[2][0] = sv[3][0] = -1e10f; }
        if (mk.y == 0) { sv[0][1] = sv[1][1] = sv[2][1] = sv[3][1] = -1e10f; }
        if (mk.z == 0) { sv[0][2] = sv[1][2] = sv[2][2] = sv[3][2] = -1e10f; }
        if (mk.w == 0) { sv[0][3] = sv[1][3] = sv[2][3] = sv[3][3] = -1e10f; }

#pragma unroll
        for (int i = 0; i < 4; i++) {
            float tm = fmaxf(fmaxf(sv[i][0], sv[i][1]), fmaxf(sv[i][2], sv[i][3]));
            tm = fmaxf(tm, __shfl_xor_sync(0xffffffffu, tm, 1));
            tm = fmaxf(tm, __shfl_xor_sync(0xffffffffu, tm, 2));
            tm = fmaxf(tm, __shfl_xor_sync(0xffffffffu, tm, 4));
            tm = fmaxf(tm, __shfl_xor_sync(0xffffffffu, tm, 8));
            float mnew  = fmaxf(rm[i], tm);
            float alpha = __expf(rm[i] - mnew);
            rm[i] = mnew;
            float p0 = __expf(sv[i][0] - mnew);
            float p1 = __expf(sv[i][1] - mnew);
            float p2 = __expf(sv[i][2] - mnew);
            float p3 = __expf(sv[i][3] - mnew);
            sv[i][0] = p0; sv[i][1] = p1; sv[i][2] = p2; sv[i][3] = p3;
            float rs = p0 + p1 + p2 + p3;
            rs += __shfl_xor_sync(0xffffffffu, rs, 1);
            rs += __shfl_xor_sync(0xffffffffu, rs, 2);
            rs += __shfl_xor_sync(0xffffffffu, rs, 4);
            rs += __shfl_xor_sync(0xffffffffu, rs, 8);
            rl[i] = rl[i] * alpha + rs;
            u64 a2 = pk2(alpha, alpha);
            o2[i][0] = fmul2(o2[i][0], a2);
            o2[i][1] = fmul2(o2[i][1], a2);
        }

        __syncthreads();
#pragma unroll
        for (int i = 0; i < 4; i++) {
            float4 pv = make_float4(sv[i][0], sv[i][1], sv[i][2], sv[i][3]);
            *(float4*)&KPs[(ty * 4 + i) * 64 + tx * 4] = pv;
        }
        __syncthreads();

#pragma unroll 4
        for (int k4 = 0; k4 < 16; k4++) {
            float4 pr[4];
#pragma unroll
            for (int i = 0; i < 4; i++)
                pr[i] = *(const float4*)&KPs[(ty * 4 + i) * 64 + k4 * 4];
#pragma unroll
            for (int kk = 0; kk < 4; kk++) {
                ulonglong2 v2 = *(const ulonglong2*)&Vs[(k4 * 4 + kk) * 64 + tx * 4];
#pragma unroll
                for (int i = 0; i < 4; i++) {
                    float pe = (kk == 0) ? pr[i].x : (kk == 1) ? pr[i].y
                             : (kk == 2) ? pr[i].z : pr[i].w;
                    u64 pp = pk2(pe, pe);
                    o2[i][0] = ffma2(pp, v2.x, o2[i][0]);
                    o2[i][1] = ffma2(pp, v2.y, o2[i][1]);
                }
            }
        }
    }

#pragma unroll
    for (int i = 0; i < 4; i++) {
        float inv = 1.0f / rl[i];
        float2 u0 = up2(o2[i][0]), u1 = up2(o2[i][1]);
        float4 o = make_float4(u0.x * inv, u0.y * inv, u1.x * inv, u1.y * inv);
        int s_ = qt * 64 + ty * 4 + i;
        *(float4*)(g_C + ((size_t)(b * SS + s_) * HIDD + h * HDD + tx * 4)) = o;
    }
}

// ---------------------------------------------------------------------------
extern "C" void kernel_launch(void* const* d_in, const int* in_sizes, int n_in,
                              void* d_out, int out_size)
{
    (void)in_sizes; (void)n_in; (void)out_size;
    const float* q    = (const float*)d_in[0];
    const float* kin  = (const float*)d_in[1];
    const float* vin  = (const float*)d_in[2];
    const int*   mask = (const int*)d_in[3];
    const float* W[4] = { (const float*)d_in[4], (const float*)d_in[5],
                          (const float*)d_in[6], (const float*)d_in[7] };
    const float* bq   = (const float*)d_in[8];
    const float* bk   = (const float*)d_in[9];
    const float* bv   = (const float*)d_in[10];
    const float* bo   = (const float*)d_in[11];
    float* out = (float*)d_out;

    float *gq, *gk, *gv, *gc;
    cudaGetSymbolAddress((void**)&gq, g_Q);
    cudaGetSymbolAddress((void**)&gk, g_K);
    cudaGetSymbolAddress((void**)&gv, g_V);
    cudaGetSymbolAddress((void**)&gc, g_C);
    __nv_bfloat16 *ahi, *alo, *whi, *wlo;
    cudaGetSymbolAddress((void**)&ahi, g_Ahi);
    cudaGetSymbolAddress((void**)&alo, g_Alo);
    cudaGetSymbolAddress((void**)&whi, g_Whi);
    cudaGetSymbolAddress((void**)&wlo, g_Wlo);

    const int nw4 = HIDD * HIDD / 4;          // 65536
    const int na4 = BB * SS * HIDD / 4;       // 1048576
    // weights -> bf16 hi/lo
    for (int i = 0; i < 4; i++)
        conv_split_kernel<<<nw4 / 256, 256>>>(W[i], whi + (size_t)i * HIDD * HIDD,
                                              wlo + (size_t)i * HIDD * HIDD, nw4);

    dim3 gg(HIDD / 128, (BB * SS) / 128);     // (4, 64)

    conv_split_kernel<<<na4 / 256, 256>>>(q, ahi, alo, na4);
    gemm_mma_kernel<<<gg, 256>>>(ahi, alo, whi + 0 * (size_t)HIDD * HIDD,
                                 wlo + 0 * (size_t)HIDD * HIDD, bq, gq, 1);
    conv_split_kernel<<<na4 / 256, 256>>>(kin, ahi, alo, na4);
    gemm_mma_kernel<<<gg, 256>>>(ahi, alo, whi + 1 * (size_t)HIDD * HIDD,
                                 wlo + 1 * (size_t)HIDD * HIDD, bk, gk, 1);
    conv_split_kernel<<<na4 / 256, 256>>>(vin, ahi, alo, na4);
    gemm_mma_kernel<<<gg, 256>>>(ahi, alo, whi + 2 * (size_t)HIDD * HIDD,
                                 wlo + 2 * (size_t)HIDD * HIDD, bv, gv, 1);

    attn_kernel<<<dim3(SS / 64, NH, BB), 256>>>(mask);

    conv_split_kernel<<<na4 / 256, 256>>>(gc, ahi, alo, na4);
    gemm_mma_kernel<<<gg, 256>>>(ahi, alo, whi + 3 * (size_t)HIDD * HIDD,
                                 wlo + 3 * (size_t)HIDD * HIDD, bo, out, 0);
}

// round 15
// speedup vs baseline: 1.0033x; 1.0033x over previous
#include <cuda_runtime.h>
#include <cuda_bf16.h>
#include <cstdint>

// MHA layer: B=4, S=2048, HID=512, H=8, HD=64.
// Projections: bf16 mma.sync (m16n8k16, HMMA path — non-arch-'a', works on
// compute_103 virtual arch) with hi/lo split 3-term compensation.
// Attention: packed-f32x2 flash attention (R8 passing version, unchanged).

#define BB   4
#define SS   2048
#define HIDD 512
#define NH   8
#define HDD  64

// ---------------- scratch (__device__ globals; no allocation allowed) -------
__device__ float g_Q[BB * NH * SS * HDD];
__device__ float g_K[BB * NH * SS * HDD];
__device__ float g_V[BB * NH * SS * HDD];
__device__ float g_C[BB * SS * HIDD];

// bf16 hi/lo split buffers (activation buffer reused sequentially for q,k,v,C)
__device__ __nv_bfloat16 g_Ahi[BB * SS * HIDD];
__device__ __nv_bfloat16 g_Alo[BB * SS * HIDD];
__device__ __nv_bfloat16 g_Whi[4][HIDD * HIDD];
__device__ __nv_bfloat16 g_Wlo[4][HIDD * HIDD];

typedef unsigned long long u64;
typedef unsigned int u32;

__device__ __forceinline__ u64 pk2(float x, float y) {
    u64 r; asm("mov.b64 %0, {%1, %2};" : "=l"(r) : "f"(x), "f"(y)); return r;
}
__device__ __forceinline__ u64 ffma2(u64 a, u64 b, u64 c) {
    u64 d; asm("fma.rn.f32x2 %0, %1, %2, %3;" : "=l"(d) : "l"(a), "l"(b), "l"(c)); return d;
}
__device__ __forceinline__ u64 fmul2(u64 a, u64 b) {
    u64 d; asm("mul.rn.f32x2 %0, %1, %2;" : "=l"(d) : "l"(a), "l"(b)); return d;
}
__device__ __forceinline__ float2 up2(u64 v) {
    float2 f; asm("mov.b64 {%0, %1}, %2;" : "=f"(f.x), "=f"(f.y) : "l"(v)); return f;
}
__device__ __forceinline__ u32 smem_u32(const void* p) {
    u32 a;
    asm("{ .reg .u64 t; cvta.to.shared.u64 t, %1; cvt.u32.u64 %0, t; }" : "=r"(a) : "l"(p));
    return a;
}

// ---------------- mma.sync helpers (sm_80+ features only) -------------------
__device__ __forceinline__ void ldmx4(u32* r, u32 addr) {
    asm volatile("ldmatrix.sync.aligned.m8n8.x4.shared.b16 {%0,%1,%2,%3}, [%4];"
        : "=r"(r[0]), "=r"(r[1]), "=r"(r[2]), "=r"(r[3]) : "r"(addr));
}
__device__ __forceinline__ void ldmx2(u32* r, u32 addr) {
    asm volatile("ldmatrix.sync.aligned.m8n8.x2.shared.b16 {%0,%1}, [%2];"
        : "=r"(r[0]), "=r"(r[1]) : "r"(addr));
}
__device__ __forceinline__ void mma16816(float* c, const u32* a, const u32* b) {
    asm volatile("mma.sync.aligned.m16n8k16.row.col.f32.bf16.bf16.f32 "
        "{%0,%1,%2,%3}, {%4,%5,%6,%7}, {%8,%9}, {%0,%1,%2,%3};"
        : "+f"(c[0]), "+f"(c[1]), "+f"(c[2]), "+f"(c[3])
        : "r"(a[0]), "r"(a[1]), "r"(a[2]), "r"(a[3]), "r"(b[0]), "r"(b[1]));
}

// ---------------------------------------------------------------------------
// fp32 -> (bf16 hi, bf16 lo) split, vectorized x4
// ---------------------------------------------------------------------------
__global__ void __launch_bounds__(256) conv_split_kernel(
    const float* __restrict__ X, __nv_bfloat16* __restrict__ hi,
    __nv_bfloat16* __restrict__ lo, int n4)
{
    int i = blockIdx.x * blockDim.x + threadIdx.x;
    if (i >= n4) return;
    float4 v = ((const float4*)X)[i];
    __nv_bfloat16 h0 = __float2bfloat16(v.x), h1 = __float2bfloat16(v.y);
    __nv_bfloat16 h2 = __float2bfloat16(v.z), h3 = __float2bfloat16(v.w);
    __nv_bfloat16 l0 = __float2bfloat16(v.x - __bfloat162float(h0));
    __nv_bfloat16 l1 = __float2bfloat16(v.y - __bfloat162float(h1));
    __nv_bfloat16 l2 = __float2bfloat16(v.z - __bfloat162float(h2));
    __nv_bfloat16 l3 = __float2bfloat16(v.w - __bfloat162float(h3));
    ((__nv_bfloat162*)hi)[2 * i + 0] = __nv_bfloat162(h0, h1);
    ((__nv_bfloat162*)hi)[2 * i + 1] = __nv_bfloat162(h2, h3);
    ((__nv_bfloat162*)lo)[2 * i + 0] = __nv_bfloat162(l0, l1);
    ((__nv_bfloat162*)lo)[2 * i + 1] = __nv_bfloat162(l2, l3);
}

// ---------------------------------------------------------------------------
// Tensor-core GEMM: Y[M][512] = A @ W^T + bias, A/W as bf16 hi/lo (K-major).
// D = Ahi*Whi + Ahi*Wlo + Alo*Whi, fp32 accumulators.
// CTA tile 128x128, 8 warps (2 m x 4 n), warp tile 64x32, K-chunk 32.
// Smem padded to stride 40 bf16 (80 B) -> conflict-free ldmatrix.
// split=1 scatters rows into [B,H,S,HD]; split=0 writes [M,512].
// ---------------------------------------------------------------------------
#define PADK 40

__global__ void __launch_bounds__(256) gemm_mma_kernel(
    const __nv_bfloat16* __restrict__ Ahi, const __nv_bfloat16* __restrict__ Alo,
    const __nv_bfloat16* __restrict__ Bhi, const __nv_bfloat16* __restrict__ Blo,
    const float* __restrict__ bias, float* __restrict__ Y, int split)
{
    __shared__ __nv_bfloat16 sAh[128 * PADK];
    __shared__ __nv_bfloat16 sAl[128 * PADK];
    __shared__ __nv_bfloat16 sBh[128 * PADK];
    __shared__ __nv_bfloat16 sBl[128 * PADK];

    const int t = threadIdx.x;
    const int lane = t & 31, wid = t >> 5;
    const int wm = wid >> 2, wn = wid & 3;     // 2 x 4 warp grid
    const int m0 = blockIdx.y * 128, n0 = blockIdx.x * 128;

    float acc[4][4][4];
#pragma unroll
    for (int i = 0; i < 4; i++)
#pragma unroll
        for (int j = 0; j < 4; j++)
#pragma unroll
            for (int q = 0; q < 4; q++) acc[i][j][q] = 0.0f;

    // ldmatrix lane addressing (element offsets)
    const int arow = lane & 15;            // A: rows 0..15 of the 16-row tile
    const int acol = (lane >> 4) * 8;      // A: k-half 0 / 8
    const int brow = lane & 7;             // B: n rows 0..7
    const int bcol = ((lane >> 3) & 1) * 8; // B: k-half for lanes 0-15

    const u32 sAh_b = smem_u32(sAh), sAl_b = smem_u32(sAl);
    const u32 sBh_b = smem_u32(sBh), sBl_b = smem_u32(sBl);

    for (int kt = 0; kt < 16; kt++) {
        const int k0 = kt * 32;
        const __nv_bfloat16* aH = Ahi + (size_t)m0 * HIDD + k0;
        const __nv_bfloat16* aL = Alo + (size_t)m0 * HIDD + k0;
        const __nv_bfloat16* bH = Bhi + (size_t)n0 * HIDD + k0;
        const __nv_bfloat16* bL = Blo + (size_t)n0 * HIDD + k0;

        __syncthreads();
        // 512 uint4 (8 bf16) per 128x32 tile; 2 per thread per tile
#pragma unroll
        for (int u = 0; u < 2; u++) {
            int e = t + u * 256;
            int row = e >> 2, c8 = (e & 3) << 3;
            int dst = row * PADK + c8;
            size_t g = (size_t)row * HIDD + c8;
            *(uint4*)&sAh[dst] = *(const uint4*)(aH + g);
            *(uint4*)&sAl[dst] = *(const uint4*)(aL + g);
            *(uint4*)&sBh[dst] = *(const uint4*)(bH + g);
            *(uint4*)&sBl[dst] = *(const uint4*)(bL + g);
        }
        __syncthreads();

#pragma unroll
        for (int k16 = 0; k16 < 32; k16 += 16) {
            // B fragments (hi + lo), 4 n-tiles of 8
            u32 bh[4][2], bl[4][2];
#pragma unroll
            for (int nt = 0; nt < 4; nt++) {
                u32 off = (u32)(((wn * 32 + nt * 8 + brow) * PADK + k16 + bcol) * 2);
                ldmx2(bh[nt], sBh_b + off);
                ldmx2(bl[nt], sBl_b + off);
            }
            // A hi fragments, 4 m-tiles of 16
            u32 ah[4][4];
#pragma unroll
            for (int mt = 0; mt < 4; mt++) {
                u32 off = (u32)(((wm * 64 + mt * 16 + arow) * PADK + k16 + acol) * 2);
                ldmx4(ah[mt], sAh_b + off);
            }
#pragma unroll
            for (int mt = 0; mt < 4; mt++)
#pragma unroll
                for (int nt = 0; nt < 4; nt++) {
                    mma16816(acc[mt][nt], ah[mt], bh[nt]);   // hi*hi
                    mma16816(acc[mt][nt], ah[mt], bl[nt]);   // hi*lo
                }
            // A lo fragments (reuse ah registers)
#pragma unroll
            for (int mt = 0; mt < 4; mt++) {
                u32 off = (u32)(((wm * 64 + mt * 16 + arow) * PADK + k16 + acol) * 2);
                ldmx4(ah[mt], sAl_b + off);
            }
#pragma unroll
            for (int mt = 0; mt < 4; mt++)
#pragma unroll
                for (int nt = 0; nt < 4; nt++)
                    mma16816(acc[mt][nt], ah[mt], bh[nt]);   // lo*hi
        }
    }

    // Epilogue: c0,c1 -> (row = m+lane/4, n = 2*(lane%4)); c2,c3 -> row+8
    const int erow = lane >> 2, ecol = (lane & 3) * 2;
#pragma unroll
    for (int mt = 0; mt < 4; mt++) {
#pragma unroll
        for (int nt = 0; nt < 4; nt++) {
            int mb = m0 + wm * 64 + mt * 16 + erow;
            int n  = n0 + wn * 32 + nt * 8 + ecol;
            float2 bb = *(const float2*)(bias + n);
            float2 o0 = make_float2(acc[mt][nt][0] + bb.x, acc[mt][nt][1] + bb.y);
            float2 o1 = make_float2(acc[mt][nt][2] + bb.x, acc[mt][nt][3] + bb.y);
            if (split) {
                int h = n >> 6, d = n & 63;
                int bi0 = mb >> 11, s0 = mb & (SS - 1);
                int m1 = mb + 8, bi1 = m1 >> 11, s1 = m1 & (SS - 1);
                *(float2*)(Y + ((((size_t)bi0 * NH + h) * SS + s0) * HDD + d)) = o0;
                *(float2*)(Y + ((((size_t)bi1 * NH + h) * SS + s1) * HDD + d)) = o1;
            } else {
                *(float2*)(Y + (size_t)mb * HIDD + n) = o0;
                *(float2*)(Y + (size_t)(mb + 8) * HIDD + n) = o1;
            }
        }
    }
}

// ---------------------------------------------------------------------------
// Flash attention (unchanged from R8 passing kernel)
// ---------------------------------------------------------------------------
__global__ void __launch_bounds__(256) attn_kernel(const int* __restrict__ mask)
{
    __shared__ float Qs[64 * 64];
    __shared__ float KPs[64 * 64];
    __shared__ float Vs[64 * 64];

    const int t  = threadIdx.x;
    const int tx = t & 15, ty = t >> 4;
    const int qt = blockIdx.x, h = blockIdx.y, b = blockIdx.z;
    const int lr = t & 63;
    const int lq = t >> 6;

    const float* Qb = g_Q + ((size_t)(b * NH + h) * SS) * HDD;
    const float* Kb = g_K + ((size_t)(b * NH + h) * SS) * HDD;
    const float* Vb = g_V + ((size_t)(b * NH + h) * SS) * HDD;
    const int*   mb = mask + b * SS;

#pragma unroll
    for (int u = 0; u < 4; u++) {
        int d4 = lq * 16 + u * 4;
        float4 v = *(const float4*)(Qb + (size_t)(qt * 64 + lr) * HDD + d4);
        Qs[(d4 + 0) * 64 + lr] = v.x; Qs[(d4 + 1) * 64 + lr] = v.y;
        Qs[(d4 + 2) * 64 + lr] = v.z; Qs[(d4 + 3) * 64 + lr] = v.w;
    }

    u64 o2[4][2];
    float rm[4], rl[4];
#pragma unroll
    for (int i = 0; i < 4; i++) {
        o2[i][0] = 0ULL; o2[i][1] = 0ULL;
        rm[i] = -1e30f; rl[i] = 0.0f;
    }

    for (int kt = 0; kt < SS / 64; kt++) {
        __syncthreads();
#pragma unroll
        for (int u = 0; u < 4; u++) {
            int d4 = lq * 16 + u * 4;
            float4 v = *(const float4*)(Kb + (size_t)(kt * 64 + lr) * HDD + d4);
            KPs[(d4 + 0) * 64 + lr] = v.x; KPs[(d4 + 1) * 64 + lr] = v.y;
            KPs[(d4 + 2) * 64 + lr] = v.z; KPs[(d4 + 3) * 64 + lr] = v.w;
        }
#pragma unroll
        for (int u = 0; u < 4; u++) {
            int f = t + u * 256;
            *(float4*)&Vs[f * 4] = *(const float4*)(Vb + (size_t)kt * 64 * HDD + f * 4);
        }
        __syncthreads();

        u64 s2[4][2];
#pragma unroll
        for (int i = 0; i < 4; i++) { s2[i][0] = 0ULL; s2[i][1] = 0ULL; }
#pragma unroll 16
        for (int d = 0; d < 64; d++) {
            float4 a4     = *(const float4*)&Qs[d * 64 + ty * 4];
            ulonglong2 b2 = *(const ulonglong2*)&KPs[d * 64 + tx * 4];
            u64 ap;
            ap = pk2(a4.x, a4.x); s2[0][0] = ffma2(ap, b2.x, s2[0][0]); s2[0][1] = ffma2(ap, b2.y, s2[0][1]);
            ap = pk2(a4.y, a4.y); s2[1][0] = ffma2(ap, b2.x, s2[1][0]); s2[1][1] = ffma2(ap, b2.y, s2[1][1]);
            ap = pk2(a4.z, a4.z); s2[2][0] = ffma2(ap, b2.x, s2[2][0]); s2[2][1] = ffma2(ap, b2.y, s2[2][1]);
            ap = pk2(a4.w, a4.w); s2[3][0] = ffma2(ap, b2.x, s2[3][0]); s2[3][1] = ffma2(ap, b2.y, s2[3][1]);
        }

        float sv[4][4];
        int4 mk = *(const int4*)(mb + kt * 64 + tx * 4);
#pragma unroll
        for (int i = 0; i < 4; i++) {
            float2 u0 = up2(s2[i][0]), u1 = up2(s2[i][1]);
            sv[i][0] = u0.x * 0.125f; sv[i][1] = u0.y * 0.125f;
            sv[i][2] = u1.x * 0.125f; sv[i][3] = u1.y * 0.125f;
        }
        if (mk.x == 0) { sv[0][0] = sv[1][0] = sv[2][0] = sv[3][0] = -1e10f; }
        if (mk.y == 0) { sv[0][1] = sv[1][1] = sv[2][1] = sv[3][1] = -1e10f; }
        if (mk.z == 0) { sv[0][2] = sv[1][2] = sv[2][2] = sv[3][2] = -1e10f; }
        if (mk.w == 0) { sv[0][3] = sv[1][3] = sv[2][3] = sv[3][3] = -1e10f; }

#pragma unroll
        for (int i = 0; i < 4; i++) {
            float tm = fmaxf(fmaxf(sv[i][0], sv[i][1]), fmaxf(sv[i][2], sv[i][3]));
            tm = fmaxf(tm, __shfl_xor_sync(0xffffffffu, tm, 1));
            tm = fmaxf(tm, __shfl_xor_sync(0xffffffffu, tm, 2));
            tm = fmaxf(tm, __shfl_xor_sync(0xffffffffu, tm, 4));
            tm = fmaxf(tm, __shfl_xor_sync(0xffffffffu, tm, 8));
            float mnew  = fmaxf(rm[i], tm);
            float alpha = __expf(rm[i] - mnew);
            rm[i] = mnew;
            float p0 = __expf(sv[i][0] - mnew);
            float p1 = __expf(sv[i][1] - mnew);
            float p2 = __expf(sv[i][2] - mnew);
            float p3 = __expf(sv[i][3] - mnew);
            sv[i][0] = p0; sv[i][1] = p1; sv[i][2] = p2; sv[i][3] = p3;
            float rs = p0 + p1 + p2 + p3;
            rs += __shfl_xor_sync(0xffffffffu, rs, 1);
            rs += __shfl_xor_sync(0xffffffffu, rs, 2);
            rs += __shfl_xor_sync(0xffffffffu, rs, 4);
            rs += __shfl_xor_sync(0xffffffffu, rs, 8);
            rl[i] = rl[i] * alpha + rs;
            u64 a2 = pk2(alpha, alpha);
            o2[i][0] = fmul2(o2[i][0], a2);
            o2[i][1] = fmul2(o2[i][1], a2);
        }

        __syncthreads();
#pragma unroll
        for (int i = 0; i < 4; i++) {
            float4 pv = make_float4(sv[i][0], sv[i][1], sv[i][2], sv[i][3]);
            *(float4*)&KPs[(ty * 4 + i) * 64 + tx * 4] = pv;
        }
        __syncthreads();

#pragma unroll 4
        for (int k4 = 0; k4 < 16; k4++) {
            float4 pr[4];
#pragma unroll
            for (int i = 0; i < 4; i++)
                pr[i] = *(const float4*)&KPs[(ty * 4 + i) * 64 + k4 * 4];
#pragma unroll
            for (int kk = 0; kk < 4; kk++) {
                ulonglong2 v2 = *(const ulonglong2*)&Vs[(k4 * 4 + kk) * 64 + tx * 4];
#pragma unroll
                for (int i = 0; i < 4; i++) {
                    float pe = (kk == 0) ? pr[i].x : (kk == 1) ? pr[i].y
                             : (kk == 2) ? pr[i].z : pr[i].w;
                    u64 pp = pk2(pe, pe);
                    o2[i][0] = ffma2(pp, v2.x, o2[i][0]);
                    o2[i][1] = ffma2(pp, v2.y, o2[i][1]);
                }
            }
        }
    }

#pragma unroll
    for (int i = 0; i < 4; i++) {
        float inv = 1.0f / rl[i];
        float2 u0 = up2(o2[i][0]), u1 = up2(o2[i][1]);
        float4 o = make_float4(u0.x * inv, u0.y * inv, u1.x * inv, u1.y * inv);
        int s_ = qt * 64 + ty * 4 + i;
        *(float4*)(g_C + ((size_t)(b * SS + s_) * HIDD + h * HDD + tx * 4)) = o;
    }
}

// ---------------------------------------------------------------------------
extern "C" void kernel_launch(void* const* d_in, const int* in_sizes, int n_in,
                              void* d_out, int out_size)
{
    (void)in_sizes; (void)n_in; (void)out_size;
    const float* q    = (const float*)d_in[0];
    const float* kin  = (const float*)d_in[1];
    const float* vin  = (const float*)d_in[2];
    const int*   mask = (const int*)d_in[3];
    const float* W[4] = { (const float*)d_in[4], (const float*)d_in[5],
                          (const float*)d_in[6], (const float*)d_in[7] };
    const float* bq   = (const float*)d_in[8];
    const float* bk   = (const float*)d_in[9];
    const float* bv   = (const float*)d_in[10];
    const float* bo   = (const float*)d_in[11];
    float* out = (float*)d_out;

    float *gq, *gk, *gv, *gc;
    cudaGetSymbolAddress((void**)&gq, g_Q);
    cudaGetSymbolAddress((void**)&gk, g_K);
    cudaGetSymbolAddress((void**)&gv, g_V);
    cudaGetSymbolAddress((void**)&gc, g_C);
    __nv_bfloat16 *ahi, *alo, *whi, *wlo;
    cudaGetSymbolAddress((void**)&ahi, g_Ahi);
    cudaGetSymbolAddress((void**)&alo, g_Alo);
    cudaGetSymbolAddress((void**)&whi, g_Whi);
    cudaGetSymbolAddress((void**)&wlo, g_Wlo);

    const int nw4 = HIDD * HIDD / 4;          // 65536
    const int na4 = BB * SS * HIDD / 4;       // 1048576
    // weights -> bf16 hi/lo
    for (int i = 0; i < 4; i++)
        conv_split_kernel<<<nw4 / 256, 256>>>(W[i], whi + (size_t)i * HIDD * HIDD,
                                              wlo + (size_t)i * HIDD * HIDD, nw4);

    dim3 gg(HIDD / 128, (BB * SS) / 128);     // (4, 64)

    conv_split_kernel<<<na4 / 256, 256>>>(q, ahi, alo, na4);
    gemm_mma_kernel<<<gg, 256>>>(ahi, alo, whi + 0 * (size_t)HIDD * HIDD,
                                 wlo + 0 * (size_t)HIDD * HIDD, bq, gq, 1);
    conv_split_kernel<<<na4 / 256, 256>>>(kin, ahi, alo, na4);
    gemm_mma_kernel<<<gg, 256>>>(ahi, alo, whi + 1 * (size_t)HIDD * HIDD,
                                 wlo + 1 * (size_t)HIDD * HIDD, bk, gk, 1);
    conv_split_kernel<<<na4 / 256, 256>>>(vin, ahi, alo, na4);
    gemm_mma_kernel<<<gg, 256>>>(ahi, alo, whi + 2 * (size_t)HIDD * HIDD,
                                 wlo + 2 * (size_t)HIDD * HIDD, bv, gv, 1);

    attn_kernel<<<dim3(SS / 64, NH, BB), 256>>>(mask);

    conv_split_kernel<<<na4 / 256, 256>>>(gc, ahi, alo, na4);
    gemm_mma_kernel<<<gg, 256>>>(ahi, alo, whi + 3 * (size_t)HIDD * HIDD,
                                 wlo + 3 * (size_t)HIDD * HIDD, bo, out, 0);
}